// round 4
// baseline (speedup 1.0000x reference)
#include <cuda_runtime.h>
#include <math_constants.h>

#define BLOCK 256
#define CHUNK 448            // pos2 points per chunk (37 chunks for N2=16384)
#define MAX_CHUNKS 64
#define MAX_N1 16384
#define MAX_RED_BLOCKS 64
#define PTS 8                // pos1 points per thread

__device__ float g_partial[MAX_CHUNKS * MAX_N1];
__device__ float g_blocksums[MAX_RED_BLOCKS];

// ---------------- packed f32x2 helpers ----------------
__device__ __forceinline__ unsigned long long f32x2_fma(unsigned long long a, unsigned long long b,
                                                        unsigned long long c) {
    unsigned long long r;
    asm("fma.rn.f32x2 %0, %1, %2, %3;" : "=l"(r) : "l"(a), "l"(b), "l"(c));
    return r;
}
__device__ __forceinline__ unsigned long long f32x2_pack(float lo, float hi) {
    unsigned long long r;
    asm("mov.b64 %0, {%1, %2};" : "=l"(r) : "f"(lo), "f"(hi));
    return r;
}
__device__ __forceinline__ float f32x2_lo(unsigned long long v) {
    float lo, hi;
    asm("mov.b64 {%0, %1}, %2;" : "=f"(lo), "=f"(hi) : "l"(v));
    return lo;
}
__device__ __forceinline__ float f32x2_hi(unsigned long long v) {
    float lo, hi;
    asm("mov.b64 {%0, %1}, %2;" : "=f"(lo), "=f"(hi) : "l"(v));
    return hi;
}

// ---------------- kernel 1 ----------------
// Each thread owns EIGHT pos1 points (4 packed f32x2 pairs). pos2 staged in
// shared as duplicated b64: nx=(-2x,-2x), ny=(-2y,-2y), c=(|p2|^2,|p2|^2).
// Per pos2 point: 4 FFMA2 (shared nx,cc -> operand reuse), 4 FFMA2 (shared ny),
// then 8 FMNMX on the alu pipe.
__global__ void __launch_bounds__(BLOCK, 2) nn_partial_kernel(
    const float* __restrict__ pos1,
    const float* __restrict__ pos2,
    int N1, int N2)
{
    __shared__ __align__(16) unsigned long long s_nx[CHUNK];
    __shared__ __align__(16) unsigned long long s_ny[CHUNK];
    __shared__ __align__(16) unsigned long long s_c[CHUNK];

    const int chunk = blockIdx.y;
    const int jbase = chunk * CHUNK;

    for (int j = threadIdx.x; j < CHUNK; j += BLOCK) {
        const int gj = jbase + j;
        float nx, ny, c;
        if (gj < N2) {
            const float x = pos2[2 * gj + 0];
            const float y = pos2[2 * gj + 1];
            nx = -2.0f * x;
            ny = -2.0f * y;
            c  = x * x + y * y;
        } else {
            nx = 0.0f; ny = 0.0f; c = 1e30f;
        }
        const unsigned long long xb = (unsigned long long)__float_as_uint(nx);
        const unsigned long long yb = (unsigned long long)__float_as_uint(ny);
        const unsigned long long cb = (unsigned long long)__float_as_uint(c);
        s_nx[j] = (xb << 32) | xb;
        s_ny[j] = (yb << 32) | yb;
        s_c[j]  = (cb << 32) | cb;
    }
    __syncthreads();

    const int t = blockIdx.x * BLOCK + threadIdx.x;   // oct index
    const int i0 = t * PTS;
    if (i0 >= N1) return;

    unsigned long long xp[4], yp[4];
    if (i0 + PTS - 1 < N1) {
#pragma unroll
        for (int k = 0; k < 4; k++) {
            const float4 p = reinterpret_cast<const float4*>(pos1)[t * 4 + k];
            xp[k] = f32x2_pack(p.x, p.z);
            yp[k] = f32x2_pack(p.y, p.w);
        }
    } else {
        float xs[PTS], ys[PTS];
#pragma unroll
        for (int k = 0; k < PTS; k++) {
            const int gi = (i0 + k < N1) ? (i0 + k) : (N1 - 1);
            xs[k] = pos1[2 * gi + 0];
            ys[k] = pos1[2 * gi + 1];
        }
#pragma unroll
        for (int k = 0; k < 4; k++) {
            xp[k] = f32x2_pack(xs[2 * k], xs[2 * k + 1]);
            yp[k] = f32x2_pack(ys[2 * k], ys[2 * k + 1]);
        }
    }

    float m[PTS];
#pragma unroll
    for (int k = 0; k < PTS; k++) m[k] = CUDART_INF_F;

    const ulonglong2* __restrict__ nx2 = reinterpret_cast<const ulonglong2*>(s_nx);
    const ulonglong2* __restrict__ ny2 = reinterpret_cast<const ulonglong2*>(s_ny);
    const ulonglong2* __restrict__ c2  = reinterpret_cast<const ulonglong2*>(s_c);

#pragma unroll 4
    for (int j = 0; j < CHUNK / 2; j++) {
        const ulonglong2 nx = nx2[j];   // LDS.128 lane-broadcast
        const ulonglong2 ny = ny2[j];
        const ulonglong2 cc = c2[j];

        // ---- pos2 point j0 ----
        {
            unsigned long long tt[4], ss[4];
#pragma unroll
            for (int k = 0; k < 4; k++) tt[k] = f32x2_fma(xp[k], nx.x, cc.x);  // reuse nx,cc
#pragma unroll
            for (int k = 0; k < 4; k++) ss[k] = f32x2_fma(yp[k], ny.x, tt[k]); // reuse ny
#pragma unroll
            for (int k = 0; k < 4; k++) {
                m[2 * k + 0] = fminf(m[2 * k + 0], f32x2_lo(ss[k]));
                m[2 * k + 1] = fminf(m[2 * k + 1], f32x2_hi(ss[k]));
            }
        }
        // ---- pos2 point j1 ----
        {
            unsigned long long tt[4], ss[4];
#pragma unroll
            for (int k = 0; k < 4; k++) tt[k] = f32x2_fma(xp[k], nx.y, cc.y);
#pragma unroll
            for (int k = 0; k < 4; k++) ss[k] = f32x2_fma(yp[k], ny.y, tt[k]);
#pragma unroll
            for (int k = 0; k < 4; k++) {
                m[2 * k + 0] = fminf(m[2 * k + 0], f32x2_lo(ss[k]));
                m[2 * k + 1] = fminf(m[2 * k + 1], f32x2_hi(ss[k]));
            }
        }
    }

    if (i0 + PTS - 1 < N1) {
#pragma unroll
        for (int k = 0; k < 2; k++) {
            float4 o;
            o.x = m[4 * k + 0]; o.y = m[4 * k + 1];
            o.z = m[4 * k + 2]; o.w = m[4 * k + 3];
            reinterpret_cast<float4*>(&g_partial[chunk * N1 + i0])[k] = o;
        }
    } else {
        for (int k = 0; k < PTS && i0 + k < N1; k++)
            g_partial[chunk * N1 + i0 + k] = m[k];
    }
}

// ---- kernel 2: min across chunks, add |p1|^2, sqrt, block partial sums ----
__global__ void __launch_bounds__(256) nn_reduce_kernel(
    const float* __restrict__ pos1, int N1, int nchunks)
{
    const int i = blockIdx.x * blockDim.x + threadIdx.x;
    float v = 0.0f;
    if (i < N1) {
        float m = CUDART_INF_F;
        for (int c = 0; c < nchunks; c++)
            m = fminf(m, g_partial[c * N1 + i]);
        const float x = pos1[2 * i + 0];
        const float y = pos1[2 * i + 1];
        const float d2 = m + (x * x + y * y);
        v = sqrtf(fmaxf(d2, 0.0f));
    }
    __shared__ float red[256];
    red[threadIdx.x] = v;
    __syncthreads();
#pragma unroll
    for (int s = 128; s > 0; s >>= 1) {
        if (threadIdx.x < s) red[threadIdx.x] += red[threadIdx.x + s];
        __syncthreads();
    }
    if (threadIdx.x == 0) g_blocksums[blockIdx.x] = red[0];
}

// ---------------- kernel 3: final deterministic sum + mean ----------------
__global__ void nn_final_kernel(float* __restrict__ out, int nblocks, float inv_n)
{
    __shared__ float red[64];
    float v = (threadIdx.x < nblocks) ? g_blocksums[threadIdx.x] : 0.0f;
    red[threadIdx.x] = v;
    __syncthreads();
#pragma unroll
    for (int s = 32; s > 0; s >>= 1) {
        if (threadIdx.x < s) red[threadIdx.x] += red[threadIdx.x + s];
        __syncthreads();
    }
    if (threadIdx.x == 0) out[0] = red[0] * inv_n;
}

// ---------------- launch ----------------
extern "C" void kernel_launch(void* const* d_in, const int* in_sizes, int n_in,
                              void* d_out, int out_size)
{
    const float* pos1 = (const float*)d_in[0];
    const float* pos2 = (const float*)d_in[1];
    float* out = (float*)d_out;

    const int N1 = in_sizes[0] / 2;
    const int N2 = in_sizes[1] / 2;

    int nchunks = (N2 + CHUNK - 1) / CHUNK;           // 37 for N2=16384
    if (nchunks > MAX_CHUNKS) nchunks = MAX_CHUNKS;

    const int octs = (N1 + PTS - 1) / PTS;            // threads (8 pos1 each)
    dim3 grid1((octs + BLOCK - 1) / BLOCK, nchunks);  // 8 x 37 = 296 = 2 * 148
    nn_partial_kernel<<<grid1, BLOCK>>>(pos1, pos2, N1, N2);

    const int red_blocks = (N1 + 255) / 256;          // 64 for N1=16384
    nn_reduce_kernel<<<red_blocks, 256>>>(pos1, N1, nchunks);

    nn_final_kernel<<<1, 64>>>(out, red_blocks, 1.0f / (float)N1);
}